// round 11
// baseline (speedup 1.0000x reference)
#include <cuda_runtime.h>

// SparseBPNeuralNetwork — fused sparse BP decoder, round 11.
// ROWS=4 with float4-packed messages: every random smem access serves 4 batch
// rows in one LDS.128, amortizing the bank-conflict max-statistic (the
// identified invariant binding resource). Dynamic smem 72.6KB, grid 512.

#define NV 648
#define NE 1944
#define BATCH 2048
#define NCHK 324
#define TOT ((size_t)BATCH * NV)
#define ROWS 4

#define VCLAMP 17.0f            // keeps products < FLT_MAX
#define TVCLAMP 14.508657f      // = 2*atanh(0.999999)
#define LN2F 0.69314718056f

// dynamic smem layout: [ s_llr4 : NV float4 ][ s_t4 : 2*NE float4 ]
#define SMEM_BYTES ((NV + 2 * NE) * 16)

// ---- preprocessed graph/weight data ----
__device__ int    g_var_of[NE];     // edge -> variable
__device__ int    g_eov[NV * 3];    // var,layer -> edge (slot = layer = e/NV)
__device__ int    g_jp[NE];         // packed partners: j1 | (j2<<16)
__device__ float2 g_w[4][NE];       // per VN layer: (W[e][j1], W[e][j2])
__device__ float  g_w9[NV][3];      // output weights per var (3 edges)

// ---------------- preprocessing ----------------
#define SCAN4 (NV * NE / 4)

__global__ void prep1(const float4* __restrict__ M_out4) {
    int idx = blockIdx.x * blockDim.x + threadIdx.x;     // over NV*NE/4
    if (idx >= SCAN4) return;
    float4 val = M_out4[idx];
    if (val.x == 0.0f && val.y == 0.0f && val.z == 0.0f && val.w == 0.0f) return;
    int lin = idx * 4;
    int v = lin / NE;
    int e = lin - v * NE;
    float vv[4] = {val.x, val.y, val.z, val.w};
#pragma unroll
    for (int k = 0; k < 4; k++) {
        if (vv[k] != 0.0f) {
            int ek = e + k;
            g_var_of[ek] = v;
            g_eov[v * 3 + ek / NV] = ek;
        }
    }
}

// one weight element per thread (8*NE threads) + W9 handled by low threads
__global__ void prep2(const float* __restrict__ W1, const float* __restrict__ W3,
                      const float* __restrict__ W5, const float* __restrict__ W7,
                      const float* __restrict__ W9) {
    int idx = blockIdx.x * blockDim.x + threadIdx.x;     // over 8*NE
    if (idx < 8 * NE) {
        int li   = idx / (2 * NE);
        int r    = idx - li * (2 * NE);
        int e    = r >> 1;
        int half = r & 1;
        int v  = g_var_of[e];
        int l  = e / NV;
        int j1 = g_eov[v * 3 + ((l + 1) % 3)];
        int j2 = g_eov[v * 3 + ((l + 2) % 3)];
        const float* W = (li == 0) ? W1 : (li == 1) ? W3 : (li == 2) ? W5 : W7;
        int j = half ? j2 : j1;
        ((float*)&g_w[li][e])[half] = W[(size_t)e * NE + j];
        if (li == 0 && half == 0) g_jp[e] = j1 | (j2 << 16);
    }
    if (idx < 3 * NV) {
        int v = idx / 3;
        int k = idx - v * 3;
        g_w9[v][k] = W9[(size_t)v * NE + g_eov[v * 3 + k]];
    }
}

// ---------------- fast math ----------------
__device__ __forceinline__ float sigmoidf(float s) {
    return __fdividef(1.0f, 1.0f + __expf(-s));
}

// fused tanh + extrinsic-product + 2*atanh for one 6-edge check, 2 rows.
__device__ __forceinline__ void cn2(const float2 v[6], float2 tv[6]) {
    float2 n[6], d[6];
#pragma unroll
    for (int k = 0; k < 6; k++) {
        float ex = __expf(fminf(v[k].x, VCLAMP));
        float ey = __expf(fminf(v[k].y, VCLAMP));
        n[k] = make_float2(ex - 1.0f, ey - 1.0f);
        d[k] = make_float2(ex + 1.0f, ey + 1.0f);
    }
#define M2(a, b) make_float2((a).x * (b).x, (a).y * (b).y)
    float2 a1 = M2(n[0], n[1]), a2 = M2(a1, n[2]), a3 = M2(a2, n[3]), a4 = M2(a3, n[4]);
    float2 b4 = M2(n[5], n[4]), b3 = M2(b4, n[3]), b2 = M2(b3, n[2]), b1 = M2(b2, n[1]);
    float2 c1 = M2(d[0], d[1]), c2 = M2(c1, d[2]), c3 = M2(c2, d[3]), c4 = M2(c3, d[4]);
    float2 f4 = M2(d[5], d[4]), f3 = M2(f4, d[3]), f2 = M2(f3, d[2]), f1 = M2(f2, d[1]);
    float2 P[6], Q[6];
    P[0] = b1;            P[1] = M2(n[0], b2);  P[2] = M2(a1, b3);
    P[3] = M2(a2, b4);    P[4] = M2(a3, n[5]);  P[5] = a4;
    Q[0] = f1;            Q[1] = M2(d[0], f2);  Q[2] = M2(c1, f3);
    Q[3] = M2(c2, f4);    Q[4] = M2(c3, d[5]);  Q[5] = c4;
#undef M2
#pragma unroll
    for (int k = 0; k < 6; k++) {
        float nx = fmaxf(Q[k].x + P[k].x, 1e-33f);
        float dx = fmaxf(Q[k].x - P[k].x, 1e-33f);
        float ny = fmaxf(Q[k].y + P[k].y, 1e-33f);
        float dy = fmaxf(Q[k].y - P[k].y, 1e-33f);
        float tx = (__log2f(nx) - __log2f(dx)) * LN2F;
        float ty = (__log2f(ny) - __log2f(dy)) * LN2F;
        tv[k].x = fminf(fmaxf(tx, -TVCLAMP), TVCLAMP);   // == clamp m to +-0.999999
        tv[k].y = fminf(fmaxf(ty, -TVCLAMP), TVCLAMP);
    }
}

__global__ __launch_bounds__(NCHK, 2)
void bp_main(const float* __restrict__ x, float* __restrict__ out) {
    extern __shared__ float4 smem[];
    float4* s_llr = smem;               // [NV]  (row0..row3)
    float4* s_t   = smem + NV;          // [2][NE] message double buffer

    const int b0  = blockIdx.x * ROWS;
    const int tid = threadIdx.x;        // one check per thread, 324 threads

    // coalesced loads of 4 rows, interleave into s_llr (float4 per var)
    {
        float2 r0 = ((const float2*)(x + (size_t)(b0 + 0) * NV))[tid];
        float2 r1 = ((const float2*)(x + (size_t)(b0 + 1) * NV))[tid];
        float2 r2 = ((const float2*)(x + (size_t)(b0 + 2) * NV))[tid];
        float2 r3 = ((const float2*)(x + (size_t)(b0 + 3) * NV))[tid];
        s_llr[2 * tid]     = make_float4(r0.x, r1.x, r2.x, r3.x);
        s_llr[2 * tid + 1] = make_float4(r0.y, r1.y, r2.y, r3.y);
    }

    const int ebase = tid * 6;
    int jp[6], vo[6];
#pragma unroll
    for (int k = 0; k < 6; k++) {
        jp[k] = g_jp[ebase + k];
        vo[k] = g_var_of[ebase + k];
    }
    const int v0 = tid, v1 = tid + NCHK;
    const int e0a = g_eov[v0 * 3 + 0], e0b = g_eov[v0 * 3 + 1], e0c = g_eov[v0 * 3 + 2];
    const int e1a = g_eov[v1 * 3 + 0], e1b = g_eov[v1 * 3 + 1], e1c = g_eov[v1 * 3 + 2];

    __syncthreads();

    // register-cache llr for this thread's 6 edges and its 2 output vars
    float4 llr_e[6];
#pragma unroll
    for (int k = 0; k < 6; k++) llr_e[k] = s_llr[vo[k]];
    const float4 llrv0 = s_llr[v0], llrv1 = s_llr[v1];

    float2 tvA[6], tvB[6];

    // ---- iteration 1: CN update directly from channel LLRs ----
    {
        float2 vinA[6], vinB[6];
#pragma unroll
        for (int k = 0; k < 6; k++) {
            vinA[k] = make_float2(llr_e[k].x, llr_e[k].y);
            vinB[k] = make_float2(llr_e[k].z, llr_e[k].w);
        }
        cn2(vinA, tvA);
        cn2(vinB, tvB);
#pragma unroll
        for (int k = 0; k < 6; k++)
            s_t[ebase + k] = make_float4(tvA[k].x, tvA[k].y, tvB[k].x, tvB[k].y);
    }
    __syncthreads();

    // out1 (offset 4*TOT)
    {
        float4 ta = s_t[e0a], tb = s_t[e0b], tc = s_t[e0c];
        float4 ua = s_t[e1a], ub = s_t[e1b], uc = s_t[e1c];
        size_t off = 4 * TOT + (size_t)b0 * NV;
        __stcs(&out[off + v0],          sigmoidf(ta.x + tb.x + tc.x + llrv0.x));
        __stcs(&out[off + v1],          sigmoidf(ua.x + ub.x + uc.x + llrv1.x));
        __stcs(&out[off + NV + v0],     sigmoidf(ta.y + tb.y + tc.y + llrv0.y));
        __stcs(&out[off + NV + v1],     sigmoidf(ua.y + ub.y + uc.y + llrv1.y));
        __stcs(&out[off + 2 * NV + v0], sigmoidf(ta.z + tb.z + tc.z + llrv0.z));
        __stcs(&out[off + 2 * NV + v1], sigmoidf(ua.z + ub.z + uc.z + llrv1.z));
        __stcs(&out[off + 3 * NV + v0], sigmoidf(ta.w + tb.w + tc.w + llrv0.w));
        __stcs(&out[off + 3 * NV + v1], sigmoidf(ua.w + ub.w + uc.w + llrv1.w));
    }

    // ---- iterations 2..5: VN update then fused CN ----
    int src = 0;
#pragma unroll
    for (int li = 0; li < 4; li++) {
        const int dst = src ^ 1;
        float2 vinA[6], vinB[6];
#pragma unroll
        for (int k = 0; k < 6; k++) {
            int j1 = jp[k] & 0xFFFF;
            int j2 = jp[k] >> 16;
            float4 t1 = s_t[src * NE + j1];      // one LDS.128 serves 4 rows
            float4 t2 = s_t[src * NE + j2];
            float2 w  = g_w[li][ebase + k];
            vinA[k].x = fmaf(w.x, t1.x, fmaf(w.y, t2.x, llr_e[k].x));
            vinA[k].y = fmaf(w.x, t1.y, fmaf(w.y, t2.y, llr_e[k].y));
            vinB[k].x = fmaf(w.x, t1.z, fmaf(w.y, t2.z, llr_e[k].z));
            vinB[k].y = fmaf(w.x, t1.w, fmaf(w.y, t2.w, llr_e[k].w));
        }
        cn2(vinA, tvA);
        cn2(vinB, tvB);
        // dst buffer was last read before the previous barrier -> safe
#pragma unroll
        for (int k = 0; k < 6; k++)
            s_t[dst * NE + ebase + k] = make_float4(tvA[k].x, tvA[k].y, tvB[k].x, tvB[k].y);
        __syncthreads();

        float4 ta = s_t[dst * NE + e0a], tb = s_t[dst * NE + e0b], tc = s_t[dst * NE + e0c];
        float4 ua = s_t[dst * NE + e1a], ub = s_t[dst * NE + e1b], uc = s_t[dst * NE + e1c];
        if (li < 3) {
            size_t off = (size_t)(3 - li) * TOT + (size_t)b0 * NV;
            __stcs(&out[off + v0],          sigmoidf(ta.x + tb.x + tc.x + llrv0.x));
            __stcs(&out[off + v1],          sigmoidf(ua.x + ub.x + uc.x + llrv1.x));
            __stcs(&out[off + NV + v0],     sigmoidf(ta.y + tb.y + tc.y + llrv0.y));
            __stcs(&out[off + NV + v1],     sigmoidf(ua.y + ub.y + uc.y + llrv1.y));
            __stcs(&out[off + 2 * NV + v0], sigmoidf(ta.z + tb.z + tc.z + llrv0.z));
            __stcs(&out[off + 2 * NV + v1], sigmoidf(ua.z + ub.z + uc.z + llrv1.z));
            __stcs(&out[off + 3 * NV + v0], sigmoidf(ta.w + tb.w + tc.w + llrv0.w));
            __stcs(&out[off + 3 * NV + v1], sigmoidf(ua.w + ub.w + uc.w + llrv1.w));
        } else {
            float w9a0 = g_w9[v0][0], w9a1 = g_w9[v0][1], w9a2 = g_w9[v0][2];
            float w9b0 = g_w9[v1][0], w9b1 = g_w9[v1][1], w9b2 = g_w9[v1][2];
            size_t off = (size_t)b0 * NV;
            __stcs(&out[off + v0],          sigmoidf(w9a0 * ta.x + w9a1 * tb.x + w9a2 * tc.x + llrv0.x));
            __stcs(&out[off + v1],          sigmoidf(w9b0 * ua.x + w9b1 * ub.x + w9b2 * uc.x + llrv1.x));
            __stcs(&out[off + NV + v0],     sigmoidf(w9a0 * ta.y + w9a1 * tb.y + w9a2 * tc.y + llrv0.y));
            __stcs(&out[off + NV + v1],     sigmoidf(w9b0 * ua.y + w9b1 * ub.y + w9b2 * uc.y + llrv1.y));
            __stcs(&out[off + 2 * NV + v0], sigmoidf(w9a0 * ta.z + w9a1 * tb.z + w9a2 * tc.z + llrv0.z));
            __stcs(&out[off + 2 * NV + v1], sigmoidf(w9b0 * ua.z + w9b1 * ub.z + w9b2 * uc.z + llrv1.z));
            __stcs(&out[off + 3 * NV + v0], sigmoidf(w9a0 * ta.w + w9a1 * tb.w + w9a2 * tc.w + llrv0.w));
            __stcs(&out[off + 3 * NV + v1], sigmoidf(w9b0 * ua.w + w9b1 * ub.w + w9b2 * uc.w + llrv1.w));
        }
        src = dst;
    }
}

// ---------------- launch ----------------
extern "C" void kernel_launch(void* const* d_in, const int* in_sizes, int n_in,
                              void* d_out, int out_size) {
    // metadata order: x, M_first, M_cn, M_out, bias_matrix, W1, W3, W5, W7, W9, B0..B4
    const float* x     = (const float*)d_in[0];
    const float* M_out = (const float*)d_in[3];
    const float* W1    = (const float*)d_in[5];
    const float* W3    = (const float*)d_in[6];
    const float* W5    = (const float*)d_in[7];
    const float* W7    = (const float*)d_in[8];
    const float* W9    = (const float*)d_in[9];

    cudaFuncSetAttribute(bp_main, cudaFuncAttributeMaxDynamicSharedMemorySize,
                         SMEM_BYTES);

    prep1<<<(SCAN4 + 255) / 256, 256>>>((const float4*)M_out);
    prep2<<<(8 * NE + 255) / 256, 256>>>(W1, W3, W5, W7, W9);
    bp_main<<<BATCH / ROWS, NCHK, SMEM_BYTES>>>(x, (float*)d_out);
}

// round 14
// speedup vs baseline: 1.4298x; 1.4298x over previous
#include <cuda_runtime.h>

// SparseBPNeuralNetwork — fused sparse BP decoder, round 12.
// Var/check two-phase layout, slot-indexed (slot = var*3 + layer):
//  * var phase: contiguous reads of own 3 messages, output + VN local,
//    stores exp2(arg) contiguously  -> zero random accesses
//  * check phase: 3 random LDS + 3 random STS per (half-check) thread
//  -> total random crossbar ops halved vs round 9 (3888 vs 7776 per blk/iter)
//  * messages in log2 domain; single-buffer smem (31KB static)

#define NV 648
#define NE 1944
#define BATCH 2048
#define NCHK 324
#define TOT ((size_t)BATCH * NV)
#define ROWS 2
#define THREADS NV

#define LOG2E 1.4426950408889634f
#define LN2F  0.69314718055994531f
#define VC2   24.52612f        // 17 * log2(e): keeps products finite
#define TL2   20.9315735f      // log2(1.999999/1e-6) == 2*atanh(0.999999)/ln2

// ---- preprocessed graph/weight data ----
__device__ int    g_eov[NV * 3];     // slot (var,layer) -> edge
__device__ int    g_slot[NE];        // edge -> slot (var*3 + layer)
__device__ float2 g_ws[4][NV * 3];   // per VN layer, per slot: (w to (l+1)%3, w to (l+2)%3)
__device__ float  g_w9[NV][3];       // output weights per var (3 slots)

// ---------------- preprocessing ----------------
#define SCAN4 (NV * NE / 4)

__global__ void prep1(const float4* __restrict__ M_out4) {
    int idx = blockIdx.x * blockDim.x + threadIdx.x;     // over NV*NE/4
    if (idx >= SCAN4) return;
    float4 val = M_out4[idx];
    if (val.x == 0.0f && val.y == 0.0f && val.z == 0.0f && val.w == 0.0f) return;
    int lin = idx * 4;
    int v = lin / NE;
    int e = lin - v * NE;
    float vv[4] = {val.x, val.y, val.z, val.w};
#pragma unroll
    for (int k = 0; k < 4; k++) {
        if (vv[k] != 0.0f) {
            int ek = e + k;
            int s  = v * 3 + ek / NV;       // layer = ek / NV
            g_slot[ek] = s;
            g_eov[s]   = ek;
        }
    }
}

__global__ void prep2(const float* __restrict__ W1, const float* __restrict__ W3,
                      const float* __restrict__ W5, const float* __restrict__ W7,
                      const float* __restrict__ W9) {
    int idx = blockIdx.x * blockDim.x + threadIdx.x;     // over 12*NV
    if (idx < 12 * NV) {
        int li = idx / (3 * NV);
        int s  = idx - li * (3 * NV);
        int v  = s / 3;
        int l  = s - v * 3;
        int e   = g_eov[s];
        int j1e = g_eov[v * 3 + ((l + 1) % 3)];
        int j2e = g_eov[v * 3 + ((l + 2) % 3)];
        const float* W = (li == 0) ? W1 : (li == 1) ? W3 : (li == 2) ? W5 : W7;
        g_ws[li][s] = make_float2(W[(size_t)e * NE + j1e], W[(size_t)e * NE + j2e]);
    }
    if (idx < 3 * NV) {
        int v = idx / 3;
        int k = idx - v * 3;
        g_w9[v][k] = W9[(size_t)v * NE + g_eov[v * 3 + k]];
    }
}

// ---------------- fast math ----------------
__device__ __forceinline__ float sigmoidf(float s) {
    return __fdividef(1.0f, 1.0f + __expf(-s));
}

// Half-check CN: this thread owns 3 of a check's 6 edges (partner = lane^1).
// ev[k] = exp(vin) per edge (rows x,y); tl[k] = log2-domain extrinsic message,
// clamped to +-TL2 (== clamp of tanh-product to +-0.999999).
__device__ __forceinline__ void cn_half(unsigned mask, const float2 ev[3], float2 tl[3]) {
    float2 n[3], d[3];
#pragma unroll
    for (int k = 0; k < 3; k++) {
        n[k] = make_float2(ev[k].x - 1.0f, ev[k].y - 1.0f);
        d[k] = make_float2(ev[k].x + 1.0f, ev[k].y + 1.0f);
    }
    // own pairwise products (leave-one-out over own 3)
    float2 n01 = make_float2(n[0].x * n[1].x, n[0].y * n[1].y);
    float2 n12 = make_float2(n[1].x * n[2].x, n[1].y * n[2].y);
    float2 n02 = make_float2(n[0].x * n[2].x, n[0].y * n[2].y);
    float2 d01 = make_float2(d[0].x * d[1].x, d[0].y * d[1].y);
    float2 d12 = make_float2(d[1].x * d[2].x, d[1].y * d[2].y);
    float2 d02 = make_float2(d[0].x * d[2].x, d[0].y * d[2].y);
    // own full 3-products -> exchange with partner half
    float pnx = n01.x * n[2].x, pny = n01.y * n[2].y;
    float pdx = d01.x * d[2].x, pdy = d01.y * d[2].y;
    float onx = __shfl_xor_sync(mask, pnx, 1);
    float ony = __shfl_xor_sync(mask, pny, 1);
    float odx = __shfl_xor_sync(mask, pdx, 1);
    float ody = __shfl_xor_sync(mask, pdy, 1);
    float2 qn[3] = {n12, n02, n01};
    float2 qd[3] = {d12, d02, d01};
#pragma unroll
    for (int k = 0; k < 3; k++) {
        float Px = qn[k].x * onx, Qx = qd[k].x * odx;   // products over the 5 others
        float Py = qn[k].y * ony, Qy = qd[k].y * ody;
        float nx = fmaxf(Qx + Px, 1e-33f), dx = fmaxf(Qx - Px, 1e-33f);
        float ny = fmaxf(Qy + Py, 1e-33f), dy = fmaxf(Qy - Py, 1e-33f);
        float tx = __log2f(nx) - __log2f(dx);
        float ty = __log2f(ny) - __log2f(dy);
        tl[k].x = fminf(fmaxf(tx, -TL2), TL2);
        tl[k].y = fminf(fmaxf(ty, -TL2), TL2);
    }
}

__global__ __launch_bounds__(THREADS, 2)
void bp_main(const float* __restrict__ x, float* __restrict__ out) {
    __shared__ float2 s_e[NV * 3];      // exp(vin) per slot (rows 0,1)
    __shared__ float2 s_tl[NV * 3];     // log2-domain messages per slot

    const int b0  = blockIdx.x * ROWS;
    const int tid = threadIdx.x;        // var role: v = tid; check role: half-check
    // 648 = 20 full warps + 8 lanes; partner (lane^1) always inside the mask
    const unsigned mask = (tid >= 640) ? 0xffu : 0xffffffffu;

    // var-role channel LLR (coalesced)
    float2 llr;
    llr.x = x[(size_t)b0 * NV + tid];
    llr.y = x[(size_t)(b0 + 1) * NV + tid];
    const float2 llr2 = make_float2(llr.x * LOG2E, llr.y * LOG2E);

    // check-role: slots of my 3 edges (check c = tid>>1, half h = tid&1)
    const int ebase = (tid >> 1) * 6 + (tid & 1) * 3;
    const int sl0 = g_slot[ebase], sl1 = g_slot[ebase + 1], sl2 = g_slot[ebase + 2];

    // ---- iteration-1 var phase: vin = llr for all 3 edges (one exp per row) ----
    {
        float2 e2;
        e2.x = exp2f(fminf(llr2.x, VC2));
        e2.y = exp2f(fminf(llr2.y, VC2));
        s_e[3 * tid]     = e2;
        s_e[3 * tid + 1] = e2;
        s_e[3 * tid + 2] = e2;
    }
    __syncthreads();

#pragma unroll
    for (int li = 0; li < 5; li++) {
        // ---- check phase: random reads of exp values, random writes of messages ----
        {
            float2 ev[3], tl[3];
            ev[0] = s_e[sl0]; ev[1] = s_e[sl1]; ev[2] = s_e[sl2];
            cn_half(mask, ev, tl);
            s_tl[sl0] = tl[0]; s_tl[sl1] = tl[1]; s_tl[sl2] = tl[2];
        }
        __syncthreads();

        // ---- var phase: everything local/contiguous ----
        float2 t0 = s_tl[3 * tid], t1 = s_tl[3 * tid + 1], t2 = s_tl[3 * tid + 2];
        if (li < 4) {
            // output li: plain message sum (+ llr), offsets 4T,3T,2T,1T
            size_t off = (size_t)(4 - li) * TOT + (size_t)b0 * NV;
            out[off + tid]      = sigmoidf(fmaf(LN2F, t0.x + t1.x + t2.x, llr.x));
            out[off + NV + tid] = sigmoidf(fmaf(LN2F, t0.y + t1.y + t2.y, llr.y));
            // VN update for next iteration, log2 domain
            float2 w0 = g_ws[li][3 * tid];
            float2 w1 = g_ws[li][3 * tid + 1];
            float2 w2 = g_ws[li][3 * tid + 2];
            float2 e0, e1, e2v;
            e0.x  = exp2f(fminf(fmaf(w0.x, t1.x, fmaf(w0.y, t2.x, llr2.x)), VC2));
            e0.y  = exp2f(fminf(fmaf(w0.x, t1.y, fmaf(w0.y, t2.y, llr2.y)), VC2));
            e1.x  = exp2f(fminf(fmaf(w1.x, t2.x, fmaf(w1.y, t0.x, llr2.x)), VC2));
            e1.y  = exp2f(fminf(fmaf(w1.x, t2.y, fmaf(w1.y, t0.y, llr2.y)), VC2));
            e2v.x = exp2f(fminf(fmaf(w2.x, t0.x, fmaf(w2.y, t1.x, llr2.x)), VC2));
            e2v.y = exp2f(fminf(fmaf(w2.x, t0.y, fmaf(w2.y, t1.y, llr2.y)), VC2));
            s_e[3 * tid]     = e0;
            s_e[3 * tid + 1] = e1;
            s_e[3 * tid + 2] = e2v;
            __syncthreads();
        } else {
            // final output (offset 0): W9-weighted message sum
            float w90 = g_w9[tid][0], w91 = g_w9[tid][1], w92 = g_w9[tid][2];
            size_t off = (size_t)b0 * NV;
            float sx = w90 * t0.x + w91 * t1.x + w92 * t2.x;
            float sy = w90 * t0.y + w91 * t1.y + w92 * t2.y;
            out[off + tid]      = sigmoidf(fmaf(LN2F, sx, llr.x));
            out[off + NV + tid] = sigmoidf(fmaf(LN2F, sy, llr.y));
        }
    }
}

// ---------------- launch ----------------
extern "C" void kernel_launch(void* const* d_in, const int* in_sizes, int n_in,
                              void* d_out, int out_size) {
    // metadata order: x, M_first, M_cn, M_out, bias_matrix, W1, W3, W5, W7, W9, B0..B4
    const float* x     = (const float*)d_in[0];
    const float* M_out = (const float*)d_in[3];
    const float* W1    = (const float*)d_in[5];
    const float* W3    = (const float*)d_in[6];
    const float* W5    = (const float*)d_in[7];
    const float* W7    = (const float*)d_in[8];
    const float* W9    = (const float*)d_in[9];

    prep1<<<(SCAN4 + 255) / 256, 256>>>((const float4*)M_out);
    prep2<<<(12 * NV + 255) / 256, 256>>>(W1, W3, W5, W7, W9);
    bp_main<<<BATCH / ROWS, THREADS>>>(x, (float*)d_out);
}